// round 17
// baseline (speedup 1.0000x reference)
#include <cuda_runtime.h>
#include <math.h>

#define REG 32               // 32x32 pixel region per block
#define NTHREADS 256         // 32x8 threads; 4 pixels/thread (rows +0,+8,+16,+24)
#define NWB 8                // warps per block
#define MAX_G 2048
#define CHUNK 1024
#define ROUNDS (CHUNK / NTHREADS)   // 4
#define MAH_CUT 37.0f
#define LOG2E 1.4426950408889634f

// ---- depth-sorted packed gaussians (Phase A output) ----
__device__ float4 g_pA[MAX_G];   // mx, my, cullR^2, a' (= -0.5*iA*log2e)
__device__ float4 g_pB[MAX_G];   // b' (= -iB*log2e), c' (= -0.5*iC*log2e), log2(opac), colR
__device__ float2 g_pC[MAX_G];   // colG, colB

// ---- software grid barrier (replay-safe: generation is monotonic) ----
__device__ unsigned g_bar_count = 0;
__device__ volatile unsigned g_bar_gen = 0;

__device__ __forceinline__ void grid_barrier(unsigned nblocks) {
    __syncthreads();
    if (threadIdx.x == 0) {
        unsigned gen = g_bar_gen;
        __threadfence();
        unsigned old = atomicAdd(&g_bar_count, 1u);
        if (old == nblocks - 1u) {
            g_bar_count = 0;
            __threadfence();
            g_bar_gen = gen + 1u;
        } else {
            while (g_bar_gen == gen) __nanosleep(32);
        }
        __threadfence();
    }
    __syncthreads();
}

__device__ __forceinline__ float ex2(float x) {
    float r;
    asm("ex2.approx.ftz.f32 %0, %1;" : "=f"(r) : "f"(x));
    return r;
}

__global__ void __launch_bounds__(NTHREADS) fused_kernel(
        const float* __restrict__ means,
        const float* __restrict__ log_scale,
        const float* __restrict__ rot,
        const float* __restrict__ colour_logits,
        const float* __restrict__ opacity_logit,
        const float* __restrict__ depth,
        int G, int W, int H, int nrx, int nreg,
        float* __restrict__ out) {
    int tid  = threadIdx.x;
    int wid  = tid >> 5;
    int lane = tid & 31;
    unsigned lmask = (1u << lane) - 1u;

    __shared__ float  sd[MAX_G];     // 8 KB: Phase A depth stage
    __shared__ float4 sA[CHUNK];     // 16 KB
    __shared__ float4 sB[CHUNK];     // 16 KB
    __shared__ float  sC[CHUNK];     // 4 KB
    __shared__ int    scnt[ROUNDS * NWB];

    // ============ Phase A: warp-per-gaussian rank + preprocess ============
    {
        // stage depths to shared (pad to multiple of 4 for float4 reads)
        int Gpad = (G + 3) & ~3;
        for (int j = tid; j < Gpad; j += NTHREADS)
            sd[j] = (j < G) ? depth[j] : 3.0e38f;
        __syncthreads();
        int G4 = Gpad >> 2;
        const float4* sd4 = (const float4*)sd;

        for (int i = blockIdx.x * NWB + wid; i < G; i += gridDim.x * NWB) {
            float di = sd[i];
            int r = 0;
#pragma unroll 8
            for (int q = lane; q < G4; q += 32) {
                float4 d = sd4[q];
                int j = q * 4;
                r += (d.x < di) || (d.x == di && (j + 0) < i);
                r += (d.y < di) || (d.y == di && (j + 1) < i);
                r += (d.z < di) || (d.z == di && (j + 2) < i);
                r += (d.w < di) || (d.w == di && (j + 3) < i);
            }
            r = __reduce_add_sync(0xffffffffu, r);

            if (lane == 0) {
                float s2x = __expf(2.f * log_scale[2 * i + 0]);
                float s2y = __expf(2.f * log_scale[2 * i + 1]);
                float s, c;
                __sincosf(rot[i], &s, &c);

                float ca = c * c * s2x + s * s * s2y;
                float cb = c * s * (s2x - s2y);
                float cd = s * s * s2x + c * c * s2y;
                float det = ca * cd - cb * cb;
                float inv = 1.f / det;
                float iA = cd * inv;
                float iB = -cb * inv;
                float iC = ca * inv;

                float opac = 1.f / (1.f + __expf(-opacity_logit[i]));
                float cr  = 1.f / (1.f + __expf(-colour_logits[3 * i + 0]));
                float cg  = 1.f / (1.f + __expf(-colour_logits[3 * i + 1]));
                float cbl = 1.f / (1.f + __expf(-colour_logits[3 * i + 2]));

                float tr = 0.5f * (ca + cd);
                float lmax = tr + sqrtf(fmaxf(tr * tr - det, 0.f));

                g_pA[r] = make_float4(means[2 * i + 0], means[2 * i + 1],
                                      MAH_CUT * lmax, -0.5f * iA * LOG2E);
                g_pB[r] = make_float4(-iB * LOG2E, -0.5f * iC * LOG2E,
                                      __log2f(opac), cr);
                g_pC[r] = make_float2(cg, cbl);
            }
        }
    }

    grid_barrier(gridDim.x);

    // ============ Phase C: one block per 32x32 region, 4 px/thread ========
    if (blockIdx.x >= (unsigned)nreg) return;

    int reg = blockIdx.x;
    int rx = reg % nrx, ry = reg / nrx;
    int px = rx * REG + (tid & 31);
    int py = ry * REG + (tid >> 5);          // rows py, py+8, py+16, py+24
    float fx = (float)px, fy = (float)py;

    float x0 = (float)(rx * REG);
    float y0 = (float)(ry * REG);
    float x1 = x0 + (float)(REG - 1);
    float y1 = y0 + (float)(REG - 1);

    float T0 = 1.f, T1 = 1.f, T2 = 1.f, T3 = 1.f;
    float aR0 = 0.f, aG0 = 0.f, aB0 = 0.f;
    float aR1 = 0.f, aG1 = 0.f, aB1 = 0.f;
    float aR2 = 0.f, aG2 = 0.f, aB2 = 0.f;
    float aR3 = 0.f, aG3 = 0.f, aB3 = 0.f;

    for (int c0 = 0; c0 < G; c0 += CHUNK) {
        // ---- prefetch cull data (independent LDG.128s) ----
        float4 Ar[ROUNDS];
        bool hr[ROUNDS];
#pragma unroll
        for (int r = 0; r < ROUNDS; r++) {
            int g = c0 + r * NTHREADS + tid;
            Ar[r] = (g < G) ? g_pA[g] : make_float4(1e30f, 1e30f, -1.f, 0.f);
        }
#pragma unroll
        for (int r = 0; r < ROUNDS; r++) {
            float ddx = fmaxf(fmaxf(x0 - Ar[r].x, Ar[r].x - x1), 0.f);
            float ddy = fmaxf(fmaxf(y0 - Ar[r].y, Ar[r].y - y1), 0.f);
            hr[r] = (ddx * ddx + ddy * ddy) <= Ar[r].z;
        }

        // early predicated loads: latency overlaps ballots/prefix/barrier
        float4 Br[ROUNDS];
        float2 Cr[ROUNDS];
#pragma unroll
        for (int r = 0; r < ROUNDS; r++) {
            if (hr[r]) {
                int g = c0 + r * NTHREADS + tid;
                Br[r] = g_pB[g];
                Cr[r] = g_pC[g];
            }
        }

        unsigned m[ROUNDS];
#pragma unroll
        for (int r = 0; r < ROUNDS; r++)
            m[r] = __ballot_sync(0xffffffffu, hr[r]);
        if (lane == 0) {
#pragma unroll
            for (int r = 0; r < ROUNDS; r++) scnt[r * NWB + wid] = __popc(m[r]);
        }
        __syncthreads();   // also guards prev-chunk composite reads

        // (round-major, warp-minor) exclusive prefix = depth order
        int offs[ROUNDS];
        int acc = 0;
#pragma unroll
        for (int r = 0; r < ROUNDS; r++) {
            int o = acc;
#pragma unroll
            for (int w = 0; w < NWB; w++) {
                int cw = scnt[r * NWB + w];
                if (w < wid) o += cw;
                acc += cw;
            }
            offs[r] = o;
        }
        int total = acc;

#pragma unroll
        for (int r = 0; r < ROUNDS; r++) {
            if (hr[r]) {
                int idx = offs[r] + __popc(m[r] & lmask);
                sA[idx] = make_float4(Ar[r].x, Ar[r].y, Ar[r].w, Br[r].x); // mx,my,a',b'
                sB[idx] = make_float4(Br[r].y, Br[r].z, Br[r].w, Cr[r].x); // c',lop,cr,cg
                sC[idx] = Cr[r].y;                                          // cb
            }
        }
        __syncthreads();

        // ---- single flat composite over compacted list (4 px/thread) ----
#pragma unroll 2
        for (int j = 0; j < total; j++) {
            float4 Aj = sA[j];
            float4 Bj = sB[j];
            float  Cj = sC[j];
            float dx  = fx - Aj.x;
            float dy0 = fy - Aj.y;
            float dy1 = dy0 + 8.f;
            float dy2 = dy0 + 16.f;
            float dy3 = dy0 + 24.f;
            float t0 = fmaf(Aj.z, dx * dx, Bj.y);   // a'*dx^2 + lop
            float u  = Aj.w * dx;                   // b'*dx
            float e0 = fmaf(Bj.x * dy0, dy0, fmaf(u, dy0, t0));
            float e1 = fmaf(Bj.x * dy1, dy1, fmaf(u, dy1, t0));
            float e2 = fmaf(Bj.x * dy2, dy2, fmaf(u, dy2, t0));
            float e3 = fmaf(Bj.x * dy3, dy3, fmaf(u, dy3, t0));
            float a0 = fminf(ex2(e0), 0.99f);
            float a1 = fminf(ex2(e1), 0.99f);
            float a2 = fminf(ex2(e2), 0.99f);
            float a3 = fminf(ex2(e3), 0.99f);
            float w0 = T0 * a0;
            float w1 = T1 * a1;
            float w2 = T2 * a2;
            float w3 = T3 * a3;
            aR0 = fmaf(w0, Bj.z, aR0); aG0 = fmaf(w0, Bj.w, aG0); aB0 = fmaf(w0, Cj, aB0);
            aR1 = fmaf(w1, Bj.z, aR1); aG1 = fmaf(w1, Bj.w, aG1); aB1 = fmaf(w1, Cj, aB1);
            aR2 = fmaf(w2, Bj.z, aR2); aG2 = fmaf(w2, Bj.w, aG2); aB2 = fmaf(w2, Cj, aB2);
            aR3 = fmaf(w3, Bj.z, aR3); aG3 = fmaf(w3, Bj.w, aG3); aB3 = fmaf(w3, Cj, aB3);
            T0 -= w0;
            T1 -= w1;
            T2 -= w2;
            T3 -= w3;
        }
    }

    if (px < W) {
        if (py < H) {
            int o = (py * W + px) * 3;
            out[o + 0] = aR0; out[o + 1] = aG0; out[o + 2] = aB0;
        }
        if (py + 8 < H) {
            int o = ((py + 8) * W + px) * 3;
            out[o + 0] = aR1; out[o + 1] = aG1; out[o + 2] = aB1;
        }
        if (py + 16 < H) {
            int o = ((py + 16) * W + px) * 3;
            out[o + 0] = aR2; out[o + 1] = aG2; out[o + 2] = aB2;
        }
        if (py + 24 < H) {
            int o = ((py + 24) * W + px) * 3;
            out[o + 0] = aR3; out[o + 1] = aG3; out[o + 2] = aB3;
        }
    }
}

extern "C" void kernel_launch(void* const* d_in, const int* in_sizes, int n_in,
                              void* d_out, int out_size) {
    const float* means         = (const float*)d_in[0];
    const float* log_scale     = (const float*)d_in[1];
    const float* rot           = (const float*)d_in[2];
    const float* colour_logits = (const float*)d_in[3];
    const float* opacity_logit = (const float*)d_in[4];
    const float* depth         = (const float*)d_in[5];

    int G = in_sizes[5];
    if (G > MAX_G) G = MAX_G;

    int HW = out_size / 3;
    int W = (int)(sqrt((double)HW) + 0.5);
    if (W <= 0) W = 1;
    int H = HW / W;

    int nrx = (W + REG - 1) / REG;
    int nry = (H + REG - 1) / REG;
    int nreg = nrx * nry;              // 144 for 384x384

    int nblocks = nreg;
    int needA = (G + NWB - 1) / NWB;
    if (nblocks < needA) nblocks = needA;

    fused_kernel<<<nblocks, NTHREADS>>>(means, log_scale, rot, colour_logits,
                                        opacity_logit, depth,
                                        G, W, H, nrx, nreg, (float*)d_out);
}